// round 3
// baseline (speedup 1.0000x reference)
#include <cuda_runtime.h>
#include <cuda_bf16.h>

#define N_MAX 50000
#define DIM 128

__device__ __align__(16) float g_h[N_MAX * DIM];
__device__ __align__(16) float g_agg[N_MAX * DIM];
__device__ float g_deg[N_MAX];
__device__ int   g_is64;

// ---------------------------------------------------------------------------
// Detect whether the edge buffer is int64 or int32.
// Indices are < 2^31, so int64 data has ALL odd 32-bit words == 0.
// For int32 data the odd words are random indices -> virtually never all zero.
// ---------------------------------------------------------------------------
__global__ void detect_kernel(const int* __restrict__ ei_words)
{
    if (threadIdx.x == 0) {
        int all_zero = 1;
        for (int i = 0; i < 128; i++)
            if (ei_words[2 * i + 1] != 0) { all_zero = 0; break; }
        g_is64 = all_zero;
    }
}

// ---------------------------------------------------------------------------
// Register-blocked fp32 GEMM:  OUT[N,128] = act( IN[N,128] @ W[128,128]^T + b )
// MODE 0: IN = X, relu, and zero g_agg/g_deg rows in epilogue (for GEMM1)
// MODE 1: IN = g_agg/deg + g_h (computed on the fly), no relu (for GEMM2)
// BM=64 rows/block, BK=32, 256 threads, each thread computes a 4x8 micro-tile.
// ---------------------------------------------------------------------------
template <int MODE>
__global__ void __launch_bounds__(256)
gemm_kernel(const float* __restrict__ X, const float* __restrict__ W,
            const float* __restrict__ bias, float* __restrict__ OUT, int N)
{
    constexpr int BM = 64, BK = 32, TM = 4, TN = 8;
    __shared__ float Wsh[BK * 132];   // Wsh[k*132 + j] = W[j][k0+k]; stride 132 keeps
                                      // float4 reads 16B-aligned (132*4 = 16*33)
    __shared__ float Xsh[BM * 33];    // pad 33 -> conflict-free A reads
    __shared__ float invd[BM];

    const int t  = threadIdx.x;
    const int tx = t & 15;            // 16 col-groups * 8 cols = 128
    const int ty = t >> 4;            // 16 row-groups * 4 rows = 64
    const int row0 = blockIdx.x * BM;

    float acc[TM][TN];
#pragma unroll
    for (int i = 0; i < TM; i++)
#pragma unroll
        for (int j = 0; j < TN; j++) acc[i][j] = 0.f;

    if (MODE == 1) {
        if (t < BM) {
            int r = row0 + t;
            float d = (r < N) ? g_deg[r] : 1.f;
            invd[t] = 1.f / fmaxf(d, 1.f);
        }
        __syncthreads();
    }

    for (int k0 = 0; k0 < DIM; k0 += BK) {
        // W tile -> k-major in smem, coalesced global reads
#pragma unroll
        for (int s = 0; s < (BK * DIM) / 256; s++) {
            int i = t + s * 256;
            int k = i & 31, j = i >> 5;
            Wsh[k * 132 + j] = W[j * DIM + k0 + k];
        }
        // input tile
#pragma unroll
        for (int s = 0; s < (BM * BK) / 256; s++) {
            int i = t + s * 256;
            int r = i >> 5, k = i & 31;
            int gr = row0 + r;
            float v = 0.f;
            if (gr < N) {
                int gi = gr * DIM + k0 + k;
                if (MODE == 0) v = X[gi];
                else           v = g_agg[gi] * invd[r] + g_h[gi];
            }
            Xsh[r * 33 + k] = v;
        }
        __syncthreads();

#pragma unroll
        for (int k = 0; k < BK; k++) {
            float a[TM];
#pragma unroll
            for (int i = 0; i < TM; i++) a[i] = Xsh[(ty * TM + i) * 33 + k];
            float4 b0 = *(const float4*)&Wsh[k * 132 + tx * 8];
            float4 b1 = *(const float4*)&Wsh[k * 132 + tx * 8 + 4];
            float bb[TN] = {b0.x, b0.y, b0.z, b0.w, b1.x, b1.y, b1.z, b1.w};
#pragma unroll
            for (int i = 0; i < TM; i++)
#pragma unroll
                for (int j = 0; j < TN; j++)
                    acc[i][j] = fmaf(a[i], bb[j], acc[i][j]);
        }
        __syncthreads();
    }

    // epilogue
    float4 bv0 = *(const float4*)&bias[tx * 8];
    float4 bv1 = *(const float4*)&bias[tx * 8 + 4];
    float bv[TN] = {bv0.x, bv0.y, bv0.z, bv0.w, bv1.x, bv1.y, bv1.z, bv1.w};

#pragma unroll
    for (int i = 0; i < TM; i++) {
        int r = row0 + ty * TM + i;
        if (r >= N) continue;
        float o[TN];
#pragma unroll
        for (int j = 0; j < TN; j++) {
            float v = acc[i][j] + bv[j];
            if (MODE == 0) v = fmaxf(v, 0.f);
            o[j] = v;
        }
        float4* dst = (float4*)&OUT[r * DIM + tx * 8];
        dst[0] = make_float4(o[0], o[1], o[2], o[3]);
        dst[1] = make_float4(o[4], o[5], o[6], o[7]);
        if (MODE == 0) {
            // zero aggregation buffers for the upcoming edge kernel
            float4* az = (float4*)&g_agg[r * DIM + tx * 8];
            az[0] = make_float4(0.f, 0.f, 0.f, 0.f);
            az[1] = make_float4(0.f, 0.f, 0.f, 0.f);
            if (tx == 0) g_deg[r] = 0.f;
        }
    }
}

// ---------------------------------------------------------------------------
// Edge scatter: one warp per edge. Each lane moves one float4 (32 lanes * 16B
// = 512B = one 128-float row). Vector red.global.add.v4.f32 -> 12.8M reductions
// instead of 51.2M scalar atomics. h fits in L2 (25.6MB), so gathers hit L2.
// ---------------------------------------------------------------------------
__global__ void __launch_bounds__(256)
edge_kernel(const void* __restrict__ ei_raw, int nE)
{
    int gid  = blockIdx.x * blockDim.x + threadIdx.x;
    int e    = gid >> 5;
    int lane = gid & 31;
    if (e >= nE) return;

    int src, dst;
    if (g_is64) {
        const long long* ei = (const long long*)ei_raw;
        src = (int)ei[e];
        dst = (int)ei[nE + e];
    } else {
        const int* ei = (const int*)ei_raw;
        src = ei[e];
        dst = ei[nE + e];
    }

    const float4 v = __ldg((const float4*)(g_h + (size_t)src * DIM) + lane);
    float4* p = (float4*)(g_agg + (size_t)dst * DIM) + lane;
    asm volatile("red.global.add.v4.f32 [%0], {%1,%2,%3,%4};"
                 :: "l"(p), "f"(v.x), "f"(v.y), "f"(v.z), "f"(v.w)
                 : "memory");
    if (lane == 0) atomicAdd(&g_deg[dst], 1.0f);
}

// ---------------------------------------------------------------------------
extern "C" void kernel_launch(void* const* d_in, const int* in_sizes, int n_in,
                              void* d_out, int out_size)
{
    const float* x  = (const float*)d_in[0];
    const void*  ei = d_in[1];
    const float* W1 = (const float*)d_in[2];
    const float* b1 = (const float*)d_in[3];
    const float* W2 = (const float*)d_in[4];
    const float* b2 = (const float*)d_in[5];
    float*       out = (float*)d_out;

    const int N  = in_sizes[0] / DIM;      // 50000
    const int nE = in_sizes[1] / 2;        // 400000

    float* h_ptr;
    cudaGetSymbolAddress((void**)&h_ptr, g_h);

    const int gemm_blocks = (N + 63) / 64;

    // 0) probe edge-index dtype (int32 vs int64)
    detect_kernel<<<1, 32>>>((const int*)ei);

    // 1) h = relu(x @ W1^T + b1); zero agg/deg
    gemm_kernel<0><<<gemm_blocks, 256>>>(x, W1, b1, h_ptr, N);

    // 2) scatter-add h[src] into agg[dst], count degrees
    const long long edge_threads = (long long)nE * 32;
    edge_kernel<<<(int)((edge_threads + 255) / 256), 256>>>(ei, nE);

    // 3) out = (agg/deg + h) @ W2^T + b2
    gemm_kernel<1><<<gemm_blocks, 256>>>(nullptr, W2, b2, out, N);
}

// round 4
// speedup vs baseline: 1.3363x; 1.3363x over previous
#include <cuda_runtime.h>
#include <cuda_bf16.h>
#include <cstdint>

#define N_MAX 50000
#define DIM 128

__device__ __align__(16) float g_h[N_MAX * DIM];
__device__ __align__(16) float g_agg[N_MAX * DIM];
__device__ float g_deg[N_MAX];
__device__ int   g_is64;

// ---------------------------------------------------------------------------
// Edge-index dtype probe: int64 data (indices < 2^31) has all odd 32-bit
// words == 0; int32 data essentially never does.
// ---------------------------------------------------------------------------
__global__ void detect_kernel(const int* __restrict__ ei_words)
{
    if (threadIdx.x == 0) {
        int all_zero = 1;
        for (int i = 0; i < 128; i++)
            if (ei_words[2 * i + 1] != 0) { all_zero = 0; break; }
        g_is64 = all_zero;
    }
}

// ---------------------------------------------------------------------------
// tf32 helpers
// ---------------------------------------------------------------------------
__device__ __forceinline__ uint32_t f2tf32(float x)
{
    uint32_t r;
    asm("cvt.rna.tf32.f32 %0, %1;" : "=r"(r) : "f"(x));
    return r;
}

__device__ __forceinline__ void mma8(float* d,
    uint32_t a0, uint32_t a1, uint32_t a2, uint32_t a3,
    uint32_t b0, uint32_t b1)
{
    asm volatile(
        "mma.sync.aligned.m16n8k8.row.col.f32.tf32.tf32.f32 "
        "{%0,%1,%2,%3}, {%4,%5,%6,%7}, {%8,%9}, {%0,%1,%2,%3};"
        : "+f"(d[0]), "+f"(d[1]), "+f"(d[2]), "+f"(d[3])
        : "r"(a0), "r"(a1), "r"(a2), "r"(a3), "r"(b0), "r"(b1));
}

// ---------------------------------------------------------------------------
// Tensor-core GEMM (tf32, 2-term Markidis split -> ~fp32 accuracy):
//   OUT[N,128] = act( IN[N,128] @ W[128,128]^T + b )
// MODE 0: IN = X, relu, zero g_agg/g_deg rows in epilogue
// MODE 1: IN = g_agg/deg + g_h (fused at smem-fill time), no relu
// Block: 256 thr (8 warps: 4 in M x 2 in N), BM=128, BN=128, BK=16.
// Each warp: 32 rows (2 m-tiles) x 64 cols (8 n-tiles), acc = 64 fp32.
// Smem stride 20 floats -> fragment loads hit all 32 banks (conflict-free).
// ---------------------------------------------------------------------------
template <int MODE>
__global__ void __launch_bounds__(256)
gemm_tc(const float* __restrict__ X, const float* __restrict__ W,
        const float* __restrict__ bias, float* __restrict__ OUT, int N)
{
    constexpr int BK = 16, LDSH = 20;
    __shared__ uint32_t Ahi[128 * LDSH], Alo[128 * LDSH];
    __shared__ uint32_t Whi[128 * LDSH], Wlo[128 * LDSH];
    __shared__ float invd[128];

    const int t    = threadIdx.x;
    const int lane = t & 31;
    const int warp = t >> 5;
    const int g    = lane >> 2;     // groupID 0..7
    const int tig  = lane & 3;      // thread-in-group 0..3
    const int wm   = warp & 3;      // 4 warps along M
    const int wn   = warp >> 2;     // 2 warps along N
    const int row0 = blockIdx.x * 128;

    float acc[2][8][4];
#pragma unroll
    for (int mt = 0; mt < 2; mt++)
#pragma unroll
        for (int nt = 0; nt < 8; nt++)
#pragma unroll
            for (int c = 0; c < 4; c++) acc[mt][nt][c] = 0.f;

    if (MODE == 1) {
        if (t < 128) {
            int r = row0 + t;
            float d = (r < N) ? g_deg[r] : 1.f;
            invd[t] = 1.f / fmaxf(d, 1.f);
        }
        __syncthreads();
    }

    // fill assignment: each thread owns 8 elements (2 float4) of one row
    const int fr = t >> 1;            // 0..127
    const int fk = (t & 1) * 8;       // 0 or 8
    const int gr = row0 + fr;

    for (int k0 = 0; k0 < DIM; k0 += BK) {
        // ---- A tile ----
        float v[8];
        if (gr < N) {
            if (MODE == 0) {
                const float4* p = (const float4*)(X + (size_t)gr * DIM + k0 + fk);
                float4 p0 = __ldg(p), p1 = __ldg(p + 1);
                v[0]=p0.x; v[1]=p0.y; v[2]=p0.z; v[3]=p0.w;
                v[4]=p1.x; v[5]=p1.y; v[6]=p1.z; v[7]=p1.w;
            } else {
                const float4* pa = (const float4*)(g_agg + (size_t)gr * DIM + k0 + fk);
                const float4* ph = (const float4*)(g_h   + (size_t)gr * DIM + k0 + fk);
                float s = invd[fr];
                float4 a0 = pa[0], a1 = pa[1], h0 = ph[0], h1 = ph[1];
                v[0]=fmaf(a0.x,s,h0.x); v[1]=fmaf(a0.y,s,h0.y);
                v[2]=fmaf(a0.z,s,h0.z); v[3]=fmaf(a0.w,s,h0.w);
                v[4]=fmaf(a1.x,s,h1.x); v[5]=fmaf(a1.y,s,h1.y);
                v[6]=fmaf(a1.z,s,h1.z); v[7]=fmaf(a1.w,s,h1.w);
            }
        } else {
#pragma unroll
            for (int j = 0; j < 8; j++) v[j] = 0.f;
        }
#pragma unroll
        for (int j = 0; j < 8; j++) {
            uint32_t hi = f2tf32(v[j]);
            float lo = v[j] - __uint_as_float(hi);
            Ahi[fr * LDSH + fk + j] = hi;
            Alo[fr * LDSH + fk + j] = f2tf32(lo);
        }
        // ---- W tile (row n = fr, always valid) ----
        {
            const float4* p = (const float4*)(W + (size_t)fr * DIM + k0 + fk);
            float4 p0 = __ldg(p), p1 = __ldg(p + 1);
            float w[8] = {p0.x,p0.y,p0.z,p0.w,p1.x,p1.y,p1.z,p1.w};
#pragma unroll
            for (int j = 0; j < 8; j++) {
                uint32_t hi = f2tf32(w[j]);
                float lo = w[j] - __uint_as_float(hi);
                Whi[fr * LDSH + fk + j] = hi;
                Wlo[fr * LDSH + fk + j] = f2tf32(lo);
            }
        }
        __syncthreads();

#pragma unroll
        for (int kk = 0; kk < BK; kk += 8) {
            // A fragments (hi + lo) for 2 m-tiles
            uint32_t ah[2][4], al[2][4];
#pragma unroll
            for (int mt = 0; mt < 2; mt++) {
                int r_ = wm * 32 + mt * 16 + g;
                int c0 = kk + tig, c1 = kk + tig + 4;
                ah[mt][0] = Ahi[r_ * LDSH + c0];
                ah[mt][1] = Ahi[(r_ + 8) * LDSH + c0];
                ah[mt][2] = Ahi[r_ * LDSH + c1];
                ah[mt][3] = Ahi[(r_ + 8) * LDSH + c1];
                al[mt][0] = Alo[r_ * LDSH + c0];
                al[mt][1] = Alo[(r_ + 8) * LDSH + c0];
                al[mt][2] = Alo[r_ * LDSH + c1];
                al[mt][3] = Alo[(r_ + 8) * LDSH + c1];
            }
#pragma unroll
            for (int nt = 0; nt < 8; nt++) {
                int n_ = wn * 64 + nt * 8 + g;
                uint32_t bh0 = Whi[n_ * LDSH + kk + tig];
                uint32_t bh1 = Whi[n_ * LDSH + kk + tig + 4];
                uint32_t bl0 = Wlo[n_ * LDSH + kk + tig];
                uint32_t bl1 = Wlo[n_ * LDSH + kk + tig + 4];
#pragma unroll
                for (int mt = 0; mt < 2; mt++) {
                    mma8(acc[mt][nt], ah[mt][0], ah[mt][1], ah[mt][2], ah[mt][3], bh0, bh1);
                    mma8(acc[mt][nt], ah[mt][0], ah[mt][1], ah[mt][2], ah[mt][3], bl0, bl1);
                    mma8(acc[mt][nt], al[mt][0], al[mt][1], al[mt][2], al[mt][3], bh0, bh1);
                }
            }
        }
        __syncthreads();
    }

    // ---- epilogue: c0:(g, 2t) c1:(g, 2t+1) c2:(g+8, 2t) c3:(g+8, 2t+1) ----
#pragma unroll
    for (int nt = 0; nt < 8; nt++) {
        int c = wn * 64 + nt * 8 + 2 * tig;
        float b0 = __ldg(bias + c), b1 = __ldg(bias + c + 1);
#pragma unroll
        for (int mt = 0; mt < 2; mt++) {
            int r_ = row0 + wm * 32 + mt * 16 + g;
            if (r_ < N) {
                float o0 = acc[mt][nt][0] + b0;
                float o1 = acc[mt][nt][1] + b1;
                if (MODE == 0) { o0 = fmaxf(o0, 0.f); o1 = fmaxf(o1, 0.f); }
                *(float2*)(OUT + (size_t)r_ * DIM + c) = make_float2(o0, o1);
            }
            int r2 = r_ + 8;
            if (r2 < N) {
                float o2 = acc[mt][nt][2] + b0;
                float o3 = acc[mt][nt][3] + b1;
                if (MODE == 0) { o2 = fmaxf(o2, 0.f); o3 = fmaxf(o3, 0.f); }
                *(float2*)(OUT + (size_t)r2 * DIM + c) = make_float2(o2, o3);
            }
        }
    }

    if (MODE == 0) {
        // zero aggregation buffers for the upcoming edge kernel
        const float4 z4 = make_float4(0.f, 0.f, 0.f, 0.f);
#pragma unroll
        for (int s = 0; s < 16; s++) {
            int idx = t + s * 256;          // 0..4095 float4 slots (128 rows x 32)
            int r = idx >> 5;
            if (row0 + r < N)
                ((float4*)(g_agg + (size_t)(row0 + r) * DIM))[idx & 31] = z4;
        }
        if (t < 128 && row0 + t < N) g_deg[row0 + t] = 0.f;
    }
}

// ---------------------------------------------------------------------------
// Edge scatter: one warp per edge; lane = one float4 of the 128-float row.
// red.global.add.v4.f32 -> 12.8M vector reductions; h (25.6MB) L2-resident.
// ---------------------------------------------------------------------------
__global__ void __launch_bounds__(256)
edge_kernel(const void* __restrict__ ei_raw, int nE)
{
    int gid  = blockIdx.x * blockDim.x + threadIdx.x;
    int e    = gid >> 5;
    int lane = gid & 31;
    if (e >= nE) return;

    int src, dst;
    if (g_is64) {
        const long long* ei = (const long long*)ei_raw;
        src = (int)ei[e];
        dst = (int)ei[nE + e];
    } else {
        const int* ei = (const int*)ei_raw;
        src = ei[e];
        dst = ei[nE + e];
    }

    const float4 v = __ldg((const float4*)(g_h + (size_t)src * DIM) + lane);
    float4* p = (float4*)(g_agg + (size_t)dst * DIM) + lane;
    asm volatile("red.global.add.v4.f32 [%0], {%1,%2,%3,%4};"
                 :: "l"(p), "f"(v.x), "f"(v.y), "f"(v.z), "f"(v.w)
                 : "memory");
    if (lane == 0) atomicAdd(&g_deg[dst], 1.0f);
}

// ---------------------------------------------------------------------------
extern "C" void kernel_launch(void* const* d_in, const int* in_sizes, int n_in,
                              void* d_out, int out_size)
{
    const float* x  = (const float*)d_in[0];
    const void*  ei = d_in[1];
    const float* W1 = (const float*)d_in[2];
    const float* b1 = (const float*)d_in[3];
    const float* W2 = (const float*)d_in[4];
    const float* b2 = (const float*)d_in[5];
    float*       out = (float*)d_out;

    const int N  = in_sizes[0] / DIM;      // 50000
    const int nE = in_sizes[1] / 2;        // 400000

    float* h_ptr;
    cudaGetSymbolAddress((void**)&h_ptr, g_h);

    const int gemm_blocks = (N + 127) / 128;

    // 0) probe edge-index dtype (int32 vs int64)
    detect_kernel<<<1, 32>>>((const int*)ei);

    // 1) h = relu(x @ W1^T + b1); zero agg/deg
    gemm_tc<0><<<gemm_blocks, 256>>>(x, W1, b1, h_ptr, N);

    // 2) scatter-add h[src] into agg[dst], count degrees
    const long long edge_threads = (long long)nE * 32;
    edge_kernel<<<(int)((edge_threads + 255) / 256), 256>>>(ei, nE);

    // 3) out = (agg/deg + h) @ W2^T + b2
    gemm_tc<1><<<gemm_blocks, 256>>>(nullptr, W2, b2, out, N);
}